// round 13
// baseline (speedup 1.0000x reference)
#include <cuda_runtime.h>
#include <cuda_fp16.h>
#include <cstdint>

#define DG 128
#define MAXN 100000
#define MAXE 1600000
#define SCB 1024
#define MAXB ((MAXN + SCB - 1) / SCB)

// Scratch (device globals — no allocation allowed).
__device__ __align__(16) float g_agg0[MAXN * 4];   // x,y,z = sum x[src]; w = deg
__device__ int g_cursor[MAXN];
__device__ int g_rowptr[MAXN + 1];
__device__ int g_csrc[MAXE];
__device__ __align__(16) __half g_hh[MAXN * DG];    // h after layer0+LN (fp16)
__device__ __align__(16) __half g_aggh[MAXN * DG];  // layer1 mean-agg (fp16)
__device__ __align__(16) __half g_wh[2 * DG * DG];  // [n][k] fp16 fused weights

// ---------------------------------------------------------------------------
// cp.async helpers
// ---------------------------------------------------------------------------
__device__ __forceinline__ void cp_async16(void* dst_smem, const void* src, bool valid) {
    uint32_t dst = (uint32_t)__cvta_generic_to_shared(dst_smem);
    int sz = valid ? 16 : 0;
    asm volatile("cp.async.cg.shared.global [%0], [%1], 16, %2;\n"
                 :: "r"(dst), "l"(src), "r"(sz));
}
#define CP_COMMIT() asm volatile("cp.async.commit_group;\n" ::: "memory")
#define CP_WAIT0()  asm volatile("cp.async.wait_group 0;\n" ::: "memory")

// ---------------------------------------------------------------------------
// 1. Prep: zero g_agg0 + fuse/convert layer-1 weights.
// ---------------------------------------------------------------------------
__global__ void prep_kernel(const float* __restrict__ Wl,
                            const float* __restrict__ Wr, int n) {
    int t = blockIdx.x * blockDim.x + threadIdx.x;
    if (t < 2 * DG * DG) {
        int k = t >> 7, nn = t & 127;
        float v = (k < DG) ? Wl[k * DG + nn] : Wr[(k - DG) * DG + nn];
        g_wh[nn * 2 * DG + k] = __float2half_rn(v);
    }
    if (t < n) ((float4*)g_agg0)[t] = make_float4(0.f, 0.f, 0.f, 0.f);
}

// ---------------------------------------------------------------------------
// 2. Edge pass 0: scatter x[src] (3 dims) + degree, one float4 RED per edge.
// ---------------------------------------------------------------------------
__global__ void edge0_kernel(const float* __restrict__ x,
                             const int* __restrict__ ei, int nE) {
    int t = blockIdx.x * blockDim.x + threadIdx.x;
    int e4 = t * 4;
    if (e4 + 4 <= nE) {
        int4 ss = *(const int4*)(ei + e4);
        int4 dd = *(const int4*)(ei + nE + e4);
        float4 v0 = make_float4(x[3 * ss.x], x[3 * ss.x + 1], x[3 * ss.x + 2], 1.f);
        float4 v1 = make_float4(x[3 * ss.y], x[3 * ss.y + 1], x[3 * ss.y + 2], 1.f);
        float4 v2 = make_float4(x[3 * ss.z], x[3 * ss.z + 1], x[3 * ss.z + 2], 1.f);
        float4 v3 = make_float4(x[3 * ss.w], x[3 * ss.w + 1], x[3 * ss.w + 2], 1.f);
        atomicAdd((float4*)(g_agg0 + 4 * (size_t)dd.x), v0);
        atomicAdd((float4*)(g_agg0 + 4 * (size_t)dd.y), v1);
        atomicAdd((float4*)(g_agg0 + 4 * (size_t)dd.z), v2);
        atomicAdd((float4*)(g_agg0 + 4 * (size_t)dd.w), v3);
    } else {
        for (int e = e4; e < nE; e++) {
            int s = ei[e], d = ei[nE + e];
            float4 v = make_float4(x[3 * s], x[3 * s + 1], x[3 * s + 2], 1.f);
            atomicAdd((float4*)(g_agg0 + 4 * (size_t)d), v);
        }
    }
}

// ---------------------------------------------------------------------------
// 3. Scan (fully merged): each block sums degrees [0, base) for its offset,
//    then in-chunk exclusive scan -> rowptr & cursor. Last block writes
//    rowptr[n]. Degrees read from g_agg0.w (exact small ints in fp32).
// ---------------------------------------------------------------------------
__global__ __launch_bounds__(256) void scan_kernel(int n) {
    int t = threadIdx.x;
    int lane = t & 31, wid = t >> 5;
    int base = blockIdx.x * SCB;

    // prefix offset: sum of all degrees before this chunk
    int ps = 0;
    for (int i = t; i < base; i += 256) ps += (int)g_agg0[4 * (size_t)i + 3];
#pragma unroll
    for (int o = 16; o; o >>= 1) ps += __shfl_xor_sync(0xffffffffu, ps, o);
    __shared__ int pwt[8];
    if (lane == 0) pwt[wid] = ps;
    __syncthreads();
    int boff = pwt[0] + pwt[1] + pwt[2] + pwt[3] +
               pwt[4] + pwt[5] + pwt[6] + pwt[7];

    // in-chunk exclusive scan (4 elements per thread)
    int i0 = base + t * 4;
    int d0 = (i0 + 0 < n) ? (int)g_agg0[4 * (size_t)(i0 + 0) + 3] : 0;
    int d1 = (i0 + 1 < n) ? (int)g_agg0[4 * (size_t)(i0 + 1) + 3] : 0;
    int d2 = (i0 + 2 < n) ? (int)g_agg0[4 * (size_t)(i0 + 2) + 3] : 0;
    int d3 = (i0 + 3 < n) ? (int)g_agg0[4 * (size_t)(i0 + 3) + 3] : 0;
    int s = d0 + d1 + d2 + d3;

    int incl = s;
#pragma unroll
    for (int o = 1; o < 32; o <<= 1) {
        int u = __shfl_up_sync(0xffffffffu, incl, o);
        if (lane >= o) incl += u;
    }
    __shared__ int wt[8];
    if (lane == 31) wt[wid] = incl;
    __syncthreads();
    if (t == 0) {
        int run = 0;
#pragma unroll
        for (int i = 0; i < 8; i++) { int u = wt[i]; wt[i] = run; run += u; }
    }
    __syncthreads();
    int run = incl - s + wt[wid] + boff;
    if (i0 + 0 < n) { g_rowptr[i0 + 0] = run; g_cursor[i0 + 0] = run; run += d0; }
    if (i0 + 1 < n) { g_rowptr[i0 + 1] = run; g_cursor[i0 + 1] = run; run += d1; }
    if (i0 + 2 < n) { g_rowptr[i0 + 2] = run; g_cursor[i0 + 2] = run; run += d2; }
    if (i0 + 3 < n) { g_rowptr[i0 + 3] = run; g_cursor[i0 + 3] = run; run += d3; }
    if (i0 < n && i0 + 4 >= n) g_rowptr[n] = run;   // thread owning last element
}

// ---------------------------------------------------------------------------
// 4. Merged fill + layer0 (independent jobs, split by block range).
// ---------------------------------------------------------------------------
__device__ __forceinline__ float warp_sum(float v) {
#pragma unroll
    for (int o = 16; o; o >>= 1) v += __shfl_xor_sync(0xffffffffu, v, o);
    return v;
}

__global__ __launch_bounds__(256) void fill_layer0_kernel(
    const int* __restrict__ ei, int nE, int nbFill,
    const float* __restrict__ x, const float* __restrict__ Wl,
    const float* __restrict__ Wr, const float* __restrict__ b,
    const float* __restrict__ g, const float* __restrict__ be, int n) {
    if (blockIdx.x < (unsigned)nbFill) {
        int t = blockIdx.x * 256 + threadIdx.x;
        int e4 = t * 4;
        if (e4 + 4 <= nE) {
            int4 ss = *(const int4*)(ei + e4);
            int4 dd = *(const int4*)(ei + nE + e4);
            int p0 = atomicAdd(&g_cursor[dd.x], 1);
            int p1 = atomicAdd(&g_cursor[dd.y], 1);
            int p2 = atomicAdd(&g_cursor[dd.z], 1);
            int p3 = atomicAdd(&g_cursor[dd.w], 1);
            g_csrc[p0] = ss.x;
            g_csrc[p1] = ss.y;
            g_csrc[p2] = ss.z;
            g_csrc[p3] = ss.w;
        } else {
            for (int e = e4; e < nE; e++) {
                int s = ei[e], d = ei[nE + e];
                int pos = atomicAdd(&g_cursor[d], 1);
                g_csrc[pos] = s;
            }
        }
        return;
    }
    // ---- layer0: warp per node, agg read directly from g_agg0 ----
    int w = ((blockIdx.x - nbFill) * 256 + threadIdx.x) >> 5;
    if (w >= n) return;
    int lane = threadIdx.x & 31;

    float4 a = ((const float4*)g_agg0)[w];
    float inv = 1.f / fmaxf(a.w, 1.f);
    float a0 = a.x * inv, a1 = a.y * inv, a2 = a.z * inv;
    float x0 = x[3 * w], x1 = x[3 * w + 1], x2 = x[3 * w + 2];

    int col = lane * 4;
    float4 wl0 = *(const float4*)&Wl[0 * DG + col];
    float4 wl1 = *(const float4*)&Wl[1 * DG + col];
    float4 wl2 = *(const float4*)&Wl[2 * DG + col];
    float4 wr0 = *(const float4*)&Wr[0 * DG + col];
    float4 wr1 = *(const float4*)&Wr[1 * DG + col];
    float4 wr2 = *(const float4*)&Wr[2 * DG + col];
    float4 bv  = *(const float4*)&b[col];

    float v0 = bv.x + a0 * wl0.x + a1 * wl1.x + a2 * wl2.x + x0 * wr0.x + x1 * wr1.x + x2 * wr2.x;
    float v1 = bv.y + a0 * wl0.y + a1 * wl1.y + a2 * wl2.y + x0 * wr0.y + x1 * wr1.y + x2 * wr2.y;
    float v2 = bv.z + a0 * wl0.z + a1 * wl1.z + a2 * wl2.z + x0 * wr0.z + x1 * wr1.z + x2 * wr2.z;
    float v3 = bv.w + a0 * wl0.w + a1 * wl1.w + a2 * wl2.w + x0 * wr0.w + x1 * wr1.w + x2 * wr2.w;
    v0 = fmaxf(v0, 0.f); v1 = fmaxf(v1, 0.f); v2 = fmaxf(v2, 0.f); v3 = fmaxf(v3, 0.f);

    float mu = warp_sum(v0 + v1 + v2 + v3) * (1.f / DG);
    float d0 = v0 - mu, d1 = v1 - mu, d2 = v2 - mu, d3 = v3 - mu;
    float var = warp_sum(d0 * d0 + d1 * d1 + d2 * d2 + d3 * d3) * (1.f / DG);
    float rs = rsqrtf(var + 1e-5f);

    float4 gv = *(const float4*)&g[col];
    float4 bev = *(const float4*)&be[col];
    half2 p0 = __floats2half2_rn(d0 * rs * gv.x + bev.x, d1 * rs * gv.y + bev.y);
    half2 p1 = __floats2half2_rn(d2 * rs * gv.z + bev.z, d3 * rs * gv.w + bev.w);
    uint2 pk = make_uint2(*(uint32_t*)&p0, *(uint32_t*)&p1);
    *(uint2*)(g_hh + (size_t)w * DG + col) = pk;
}

// ---------------------------------------------------------------------------
// 5. Layer 1 aggregation: 16 lanes per node (2 nodes/warp), uint4 loads.
// ---------------------------------------------------------------------------
__global__ __launch_bounds__(256) void agg_kernel(int n) {
    int gw = (blockIdx.x * blockDim.x + threadIdx.x) >> 5;
    int lane = threadIdx.x & 31;
    int node = gw * 2 + (lane >> 4);
    if (node >= n) return;
    int l16 = lane & 15;
    int r0 = g_rowptr[node], r1 = g_rowptr[node + 1];
    const uint4* hh = (const uint4*)g_hh;

    float a0 = 0.f, a1 = 0.f, a2 = 0.f, a3 = 0.f;
    float a4 = 0.f, a5 = 0.f, a6 = 0.f, a7 = 0.f;
    int j = r0;
    for (; j + 4 <= r1; j += 4) {
        uint4 u[4];
#pragma unroll
        for (int q = 0; q < 4; q++) {
            int s = g_csrc[j + q];
            u[q] = hh[(size_t)s * 16 + l16];
        }
#pragma unroll
        for (int q = 0; q < 4; q++) {
            float2 f0 = __half22float2(*(half2*)&u[q].x);
            float2 f1 = __half22float2(*(half2*)&u[q].y);
            float2 f2 = __half22float2(*(half2*)&u[q].z);
            float2 f3 = __half22float2(*(half2*)&u[q].w);
            a0 += f0.x; a1 += f0.y; a2 += f1.x; a3 += f1.y;
            a4 += f2.x; a5 += f2.y; a6 += f3.x; a7 += f3.y;
        }
    }
    for (; j < r1; j++) {
        int s = g_csrc[j];
        uint4 u = hh[(size_t)s * 16 + l16];
        float2 f0 = __half22float2(*(half2*)&u.x);
        float2 f1 = __half22float2(*(half2*)&u.y);
        float2 f2 = __half22float2(*(half2*)&u.z);
        float2 f3 = __half22float2(*(half2*)&u.w);
        a0 += f0.x; a1 += f0.y; a2 += f1.x; a3 += f1.y;
        a4 += f2.x; a5 += f2.y; a6 += f3.x; a7 += f3.y;
    }
    float inv = 1.f / fmaxf((float)(r1 - r0), 1.f);
    half2 p0 = __floats2half2_rn(a0 * inv, a1 * inv);
    half2 p1 = __floats2half2_rn(a2 * inv, a3 * inv);
    half2 p2 = __floats2half2_rn(a4 * inv, a5 * inv);
    half2 p3 = __floats2half2_rn(a6 * inv, a7 * inv);
    uint4 pk = make_uint4(*(uint32_t*)&p0, *(uint32_t*)&p1,
                          *(uint32_t*)&p2, *(uint32_t*)&p3);
    ((uint4*)g_aggh)[(size_t)node * 16 + l16] = pk;
}

// ---------------------------------------------------------------------------
// 6. Layer 1 output GEMM + relu, fp16 mma.m16n8k16, cp.async double-buffered
//    (one __syncthreads per K-chunk; staging overlaps MMA).
// ---------------------------------------------------------------------------
#define ASTR 40
__global__ __launch_bounds__(256) void out_kernel(
    const float* __restrict__ bias, float* __restrict__ out, int n) {
    __shared__ __align__(16) __half sA[2][128][ASTR];
    __shared__ __align__(16) __half sB[2][128][ASTR];

    int tid = threadIdx.x;
    int wid = tid >> 5;
    int lane = tid & 31;
    int wm = wid >> 1;
    int wn = wid & 1;
    int gid = lane >> 2;
    int tg = lane & 3;
    int n0 = blockIdx.x * 128;

    int sr = tid >> 2;        // staging row 0..63 (x2 via +64)
    int sp = tid & 3;         // staging part 0..3

    float acc[2][8][4];
#pragma unroll
    for (int mt = 0; mt < 2; mt++)
#pragma unroll
        for (int nt = 0; nt < 8; nt++)
#pragma unroll
            for (int i = 0; i < 4; i++) acc[mt][nt][i] = 0.f;

    // stage chunk c into buffer c&1
    auto stage = [&](int c) {
        int buf = c & 1;
        const __half* srcA = (c < 4) ? g_aggh : g_hh;
        int ka = (c & 3) * 32;
#pragma unroll
        for (int h = 0; h < 2; h++) {
            int r = sr + h * 64;
            bool valid = (n0 + r) < n;
            int rc = valid ? (n0 + r) : 0;
            cp_async16(&sA[buf][r][sp * 8],
                       srcA + (size_t)rc * DG + ka + sp * 8, valid);
            cp_async16(&sB[buf][r][sp * 8],
                       g_wh + (size_t)r * 2 * DG + c * 32 + sp * 8, true);
        }
    };

    stage(0);
    CP_COMMIT();

#pragma unroll 1
    for (int c = 0; c < 8; c++) {
        CP_WAIT0();
        __syncthreads();
        if (c < 7) {
            stage(c + 1);
            CP_COMMIT();
        }
        int buf = c & 1;
#pragma unroll
        for (int ks = 0; ks < 2; ks++) {
            int ko = ks * 16;
            uint32_t bf[8][2];
#pragma unroll
            for (int nt = 0; nt < 8; nt++) {
                int ncol = wn * 64 + nt * 8 + gid;
                bf[nt][0] = *(uint32_t*)&sB[buf][ncol][ko + 2 * tg];
                bf[nt][1] = *(uint32_t*)&sB[buf][ncol][ko + 2 * tg + 8];
            }
#pragma unroll
            for (int mt = 0; mt < 2; mt++) {
                int r = wm * 32 + mt * 16 + gid;
                uint32_t a0 = *(uint32_t*)&sA[buf][r][ko + 2 * tg];
                uint32_t a1 = *(uint32_t*)&sA[buf][r + 8][ko + 2 * tg];
                uint32_t a2 = *(uint32_t*)&sA[buf][r][ko + 2 * tg + 8];
                uint32_t a3 = *(uint32_t*)&sA[buf][r + 8][ko + 2 * tg + 8];
#pragma unroll
                for (int nt = 0; nt < 8; nt++) {
                    asm volatile(
                        "mma.sync.aligned.m16n8k16.row.col.f32.f16.f16.f32 "
                        "{%0,%1,%2,%3}, {%4,%5,%6,%7}, {%8,%9}, {%0,%1,%2,%3};"
                        : "+f"(acc[mt][nt][0]), "+f"(acc[mt][nt][1]),
                          "+f"(acc[mt][nt][2]), "+f"(acc[mt][nt][3])
                        : "r"(a0), "r"(a1), "r"(a2), "r"(a3),
                          "r"(bf[nt][0]), "r"(bf[nt][1]));
                }
            }
        }
    }

#pragma unroll
    for (int nt = 0; nt < 8; nt++) {
        int col = wn * 64 + nt * 8 + 2 * tg;
        float2 bv = *(const float2*)&bias[col];
#pragma unroll
        for (int mt = 0; mt < 2; mt++) {
            int row = n0 + wm * 32 + mt * 16 + gid;
            if (row < n) {
                float2 o;
                o.x = fmaxf(acc[mt][nt][0] + bv.x, 0.f);
                o.y = fmaxf(acc[mt][nt][1] + bv.y, 0.f);
                *(float2*)&out[(size_t)row * DG + col] = o;
            }
            if (row + 8 < n) {
                float2 o;
                o.x = fmaxf(acc[mt][nt][2] + bv.x, 0.f);
                o.y = fmaxf(acc[mt][nt][3] + bv.y, 0.f);
                *(float2*)&out[(size_t)(row + 8) * DG + col] = o;
            }
        }
    }
}

// ---------------------------------------------------------------------------
extern "C" void kernel_launch(void* const* d_in, const int* in_sizes, int n_in,
                              void* d_out, int out_size) {
    const float* x   = (const float*)d_in[0];
    const int*   ei  = (const int*)d_in[1];
    const float* Wl0 = (const float*)d_in[2];
    const float* Wr0 = (const float*)d_in[3];
    const float* b0  = (const float*)d_in[4];
    const float* Wl1 = (const float*)d_in[5];
    const float* Wr1 = (const float*)d_in[6];
    const float* b1  = (const float*)d_in[7];
    const float* g   = (const float*)d_in[8];
    const float* be  = (const float*)d_in[9];
    float* out = (float*)d_out;

    int n  = in_sizes[0] / 3;
    int nE = in_sizes[1] / 2;
    int nb = (n + SCB - 1) / SCB;
    int prepN = (n > 2 * DG * DG) ? n : 2 * DG * DG;
    int e4threads = (nE + 3) / 4;
    int nbFill = (e4threads + 255) / 256;
    int nbL0 = (n * 32 + 255) / 256;

    prep_kernel<<<(prepN + 255) / 256, 256>>>(Wl1, Wr1, n);
    edge0_kernel<<<(e4threads + 255) / 256, 256>>>(x, ei, nE);
    scan_kernel<<<nb, 256>>>(n);
    fill_layer0_kernel<<<nbFill + nbL0, 256>>>(ei, nE, nbFill,
                                               x, Wl0, Wr0, b0, g, be, n);
    int aggWarps = (n + 1) / 2;
    agg_kernel<<<(aggWarps * 32 + 255) / 256, 256>>>(n);
    out_kernel<<<(n + 127) / 128, 256>>>(b1, out, n);
}

// round 14
// speedup vs baseline: 1.0727x; 1.0727x over previous
#include <cuda_runtime.h>
#include <cuda_fp16.h>
#include <cstdint>

#define DG 128
#define MAXN 100000
#define MAXE 1600000
#define SCB 1024
#define MAXB ((MAXN + SCB - 1) / SCB)

// Scratch (device globals — no allocation allowed).
__device__ __align__(16) float g_agg0[MAXN * 4];   // x,y,z = sum x[src]; w = deg
__device__ int g_cursor[MAXN];
__device__ int g_rowptr[MAXN + 1];
__device__ int g_csrc[MAXE];
__device__ int g_bsum[MAXB];
__device__ __align__(16) __half g_hh[MAXN * DG];    // h after layer0+LN (fp16)
__device__ __align__(16) __half g_aggh[MAXN * DG];  // layer1 mean-agg (fp16)
__device__ __align__(16) __half g_wh[2 * DG * DG];  // [n][k] fp16 fused weights

// ---------------------------------------------------------------------------
// 1. Prep: zero g_agg0 + fuse/convert layer-1 weights.
// ---------------------------------------------------------------------------
__global__ void prep_kernel(const float* __restrict__ Wl,
                            const float* __restrict__ Wr, int n) {
    int t = blockIdx.x * blockDim.x + threadIdx.x;
    if (t < 2 * DG * DG) {
        int k = t >> 7, nn = t & 127;
        float v = (k < DG) ? Wl[k * DG + nn] : Wr[(k - DG) * DG + nn];
        g_wh[nn * 2 * DG + k] = __float2half_rn(v);
    }
    if (t < n) ((float4*)g_agg0)[t] = make_float4(0.f, 0.f, 0.f, 0.f);
}

// ---------------------------------------------------------------------------
// 2. Edge pass 0: scatter x[src] (3 dims) + degree, one float4 RED per edge.
// ---------------------------------------------------------------------------
__global__ void edge0_kernel(const float* __restrict__ x,
                             const int* __restrict__ ei, int nE) {
    int t = blockIdx.x * blockDim.x + threadIdx.x;
    int e4 = t * 4;
    if (e4 + 4 <= nE) {
        int4 ss = *(const int4*)(ei + e4);
        int4 dd = *(const int4*)(ei + nE + e4);
        float4 v0 = make_float4(x[3 * ss.x], x[3 * ss.x + 1], x[3 * ss.x + 2], 1.f);
        float4 v1 = make_float4(x[3 * ss.y], x[3 * ss.y + 1], x[3 * ss.y + 2], 1.f);
        float4 v2 = make_float4(x[3 * ss.z], x[3 * ss.z + 1], x[3 * ss.z + 2], 1.f);
        float4 v3 = make_float4(x[3 * ss.w], x[3 * ss.w + 1], x[3 * ss.w + 2], 1.f);
        atomicAdd((float4*)(g_agg0 + 4 * (size_t)dd.x), v0);
        atomicAdd((float4*)(g_agg0 + 4 * (size_t)dd.y), v1);
        atomicAdd((float4*)(g_agg0 + 4 * (size_t)dd.z), v2);
        atomicAdd((float4*)(g_agg0 + 4 * (size_t)dd.w), v3);
    } else {
        for (int e = e4; e < nE; e++) {
            int s = ei[e], d = ei[nE + e];
            float4 v = make_float4(x[3 * s], x[3 * s + 1], x[3 * s + 2], 1.f);
            atomicAdd((float4*)(g_agg0 + 4 * (size_t)d), v);
        }
    }
}

// ---------------------------------------------------------------------------
// 3. Per-chunk degree sums (degree read from g_agg0.w).
// ---------------------------------------------------------------------------
__global__ __launch_bounds__(256) void bsum_kernel(int n) {
    int base = blockIdx.x * SCB;
    int t = threadIdx.x;
    int s = 0;
#pragma unroll
    for (int q = 0; q < 4; q++) {
        int i = base + t + q * 256;
        if (i < n) s += (int)g_agg0[4 * (size_t)i + 3];
    }
#pragma unroll
    for (int o = 16; o; o >>= 1) s += __shfl_xor_sync(0xffffffffu, s, o);
    __shared__ int wt[8];
    if ((t & 31) == 0) wt[t >> 5] = s;
    __syncthreads();
    if (t == 0) {
        int tot = 0;
#pragma unroll
        for (int i = 0; i < 8; i++) tot += wt[i];
        g_bsum[blockIdx.x] = tot;
    }
}

// ---------------------------------------------------------------------------
// 4. Scan: each block scans the <=128 block sums for its offset, then does
//    its in-chunk exclusive scan -> rowptr & cursor.
// ---------------------------------------------------------------------------
__global__ __launch_bounds__(256) void scan_chunk_kernel(int nb, int n) {
    __shared__ int sincl[128];
    int t = threadIdx.x;
    int lane = t & 31, wid = t >> 5;

    if (t < 128) {
        int v = (t < nb) ? g_bsum[t] : 0;
        int incl = v;
#pragma unroll
        for (int o = 1; o < 32; o <<= 1) {
            int u = __shfl_up_sync(0xffffffffu, incl, o);
            if (lane >= o) incl += u;
        }
        sincl[t] = incl;
    }
    __syncthreads();
    if (t == 0) {
        int o1 = sincl[31], o2 = sincl[63], o3 = sincl[95];
        for (int i = 32; i < 64; i++) sincl[i] += o1;
        o2 += o1;
        for (int i = 64; i < 96; i++) sincl[i] += o2;
        o3 += o2;
        for (int i = 96; i < 128; i++) sincl[i] += o3;
    }
    __syncthreads();
    int boff = (blockIdx.x == 0) ? 0 : sincl[blockIdx.x - 1];
    if (blockIdx.x == 0 && t == 0) g_rowptr[n] = sincl[nb - 1];

    int base = blockIdx.x * SCB;
    int i0 = base + t * 4;
    int d0 = (i0 + 0 < n) ? (int)g_agg0[4 * (size_t)(i0 + 0) + 3] : 0;
    int d1 = (i0 + 1 < n) ? (int)g_agg0[4 * (size_t)(i0 + 1) + 3] : 0;
    int d2 = (i0 + 2 < n) ? (int)g_agg0[4 * (size_t)(i0 + 2) + 3] : 0;
    int d3 = (i0 + 3 < n) ? (int)g_agg0[4 * (size_t)(i0 + 3) + 3] : 0;
    int s = d0 + d1 + d2 + d3;

    int incl = s;
#pragma unroll
    for (int o = 1; o < 32; o <<= 1) {
        int u = __shfl_up_sync(0xffffffffu, incl, o);
        if (lane >= o) incl += u;
    }
    __shared__ int wt[8];
    if (lane == 31) wt[wid] = incl;
    __syncthreads();
    if (t == 0) {
        int run = 0;
#pragma unroll
        for (int i = 0; i < 8; i++) { int u = wt[i]; wt[i] = run; run += u; }
    }
    __syncthreads();
    int run = incl - s + wt[wid] + boff;
    if (i0 + 0 < n) { g_rowptr[i0 + 0] = run; g_cursor[i0 + 0] = run; run += d0; }
    if (i0 + 1 < n) { g_rowptr[i0 + 1] = run; g_cursor[i0 + 1] = run; run += d1; }
    if (i0 + 2 < n) { g_rowptr[i0 + 2] = run; g_cursor[i0 + 2] = run; run += d2; }
    if (i0 + 3 < n) { g_rowptr[i0 + 3] = run; g_cursor[i0 + 3] = run; run += d3; }
}

// ---------------------------------------------------------------------------
// 5. Merged fill + layer0. Layer0: warp handles NPW nodes, weights loaded
//    into registers ONCE per warp (8x fewer weight LDGs than warp-per-node).
// ---------------------------------------------------------------------------
__device__ __forceinline__ float warp_sum(float v) {
#pragma unroll
    for (int o = 16; o; o >>= 1) v += __shfl_xor_sync(0xffffffffu, v, o);
    return v;
}

#define NPW 8   // nodes per warp in layer0
__global__ __launch_bounds__(256) void fill_layer0_kernel(
    const int* __restrict__ ei, int nE, int nbFill,
    const float* __restrict__ x, const float* __restrict__ Wl,
    const float* __restrict__ Wr, const float* __restrict__ b,
    const float* __restrict__ g, const float* __restrict__ be, int n) {
    if (blockIdx.x < (unsigned)nbFill) {
        int t = blockIdx.x * 256 + threadIdx.x;
        int e4 = t * 4;
        if (e4 + 4 <= nE) {
            int4 ss = *(const int4*)(ei + e4);
            int4 dd = *(const int4*)(ei + nE + e4);
            int p0 = atomicAdd(&g_cursor[dd.x], 1);
            int p1 = atomicAdd(&g_cursor[dd.y], 1);
            int p2 = atomicAdd(&g_cursor[dd.z], 1);
            int p3 = atomicAdd(&g_cursor[dd.w], 1);
            g_csrc[p0] = ss.x;
            g_csrc[p1] = ss.y;
            g_csrc[p2] = ss.z;
            g_csrc[p3] = ss.w;
        } else {
            for (int e = e4; e < nE; e++) {
                int s = ei[e], d = ei[nE + e];
                int pos = atomicAdd(&g_cursor[d], 1);
                g_csrc[pos] = s;
            }
        }
        return;
    }
    // ---- layer0: warp handles NPW nodes; weights register-resident ----
    int warpIdx = (blockIdx.x - nbFill) * 8 + (threadIdx.x >> 5);
    int node0 = warpIdx * NPW;
    if (node0 >= n) return;
    int lane = threadIdx.x & 31;
    int col = lane * 4;

    float4 wl0 = *(const float4*)&Wl[0 * DG + col];
    float4 wl1 = *(const float4*)&Wl[1 * DG + col];
    float4 wl2 = *(const float4*)&Wl[2 * DG + col];
    float4 wr0 = *(const float4*)&Wr[0 * DG + col];
    float4 wr1 = *(const float4*)&Wr[1 * DG + col];
    float4 wr2 = *(const float4*)&Wr[2 * DG + col];
    float4 bv  = *(const float4*)&b[col];
    float4 gv  = *(const float4*)&g[col];
    float4 bev = *(const float4*)&be[col];

#pragma unroll
    for (int i = 0; i < NPW; i++) {
        int w = node0 + i;
        if (w >= n) break;
        float4 a = ((const float4*)g_agg0)[w];
        float inv = 1.f / fmaxf(a.w, 1.f);
        float a0 = a.x * inv, a1 = a.y * inv, a2 = a.z * inv;
        float x0 = x[3 * w], x1 = x[3 * w + 1], x2 = x[3 * w + 2];

        float v0 = bv.x + a0 * wl0.x + a1 * wl1.x + a2 * wl2.x + x0 * wr0.x + x1 * wr1.x + x2 * wr2.x;
        float v1 = bv.y + a0 * wl0.y + a1 * wl1.y + a2 * wl2.y + x0 * wr0.y + x1 * wr1.y + x2 * wr2.y;
        float v2 = bv.z + a0 * wl0.z + a1 * wl1.z + a2 * wl2.z + x0 * wr0.z + x1 * wr1.z + x2 * wr2.z;
        float v3 = bv.w + a0 * wl0.w + a1 * wl1.w + a2 * wl2.w + x0 * wr0.w + x1 * wr1.w + x2 * wr2.w;
        v0 = fmaxf(v0, 0.f); v1 = fmaxf(v1, 0.f); v2 = fmaxf(v2, 0.f); v3 = fmaxf(v3, 0.f);

        float mu = warp_sum(v0 + v1 + v2 + v3) * (1.f / DG);
        float d0 = v0 - mu, d1 = v1 - mu, d2 = v2 - mu, d3 = v3 - mu;
        float var = warp_sum(d0 * d0 + d1 * d1 + d2 * d2 + d3 * d3) * (1.f / DG);
        float rs = rsqrtf(var + 1e-5f);

        half2 p0 = __floats2half2_rn(d0 * rs * gv.x + bev.x, d1 * rs * gv.y + bev.y);
        half2 p1 = __floats2half2_rn(d2 * rs * gv.z + bev.z, d3 * rs * gv.w + bev.w);
        uint2 pk = make_uint2(*(uint32_t*)&p0, *(uint32_t*)&p1);
        *(uint2*)(g_hh + (size_t)w * DG + col) = pk;
    }
}

// ---------------------------------------------------------------------------
// 6. Layer 1 aggregation: 16 lanes per node (2 nodes/warp), uint4 loads.
// ---------------------------------------------------------------------------
__global__ __launch_bounds__(256) void agg_kernel(int n) {
    int gw = (blockIdx.x * blockDim.x + threadIdx.x) >> 5;
    int lane = threadIdx.x & 31;
    int node = gw * 2 + (lane >> 4);
    if (node >= n) return;
    int l16 = lane & 15;
    int r0 = g_rowptr[node], r1 = g_rowptr[node + 1];
    const uint4* hh = (const uint4*)g_hh;

    float a0 = 0.f, a1 = 0.f, a2 = 0.f, a3 = 0.f;
    float a4 = 0.f, a5 = 0.f, a6 = 0.f, a7 = 0.f;
    int j = r0;
    for (; j + 4 <= r1; j += 4) {
        uint4 u[4];
#pragma unroll
        for (int q = 0; q < 4; q++) {
            int s = g_csrc[j + q];
            u[q] = hh[(size_t)s * 16 + l16];
        }
#pragma unroll
        for (int q = 0; q < 4; q++) {
            float2 f0 = __half22float2(*(half2*)&u[q].x);
            float2 f1 = __half22float2(*(half2*)&u[q].y);
            float2 f2 = __half22float2(*(half2*)&u[q].z);
            float2 f3 = __half22float2(*(half2*)&u[q].w);
            a0 += f0.x; a1 += f0.y; a2 += f1.x; a3 += f1.y;
            a4 += f2.x; a5 += f2.y; a6 += f3.x; a7 += f3.y;
        }
    }
    for (; j < r1; j++) {
        int s = g_csrc[j];
        uint4 u = hh[(size_t)s * 16 + l16];
        float2 f0 = __half22float2(*(half2*)&u.x);
        float2 f1 = __half22float2(*(half2*)&u.y);
        float2 f2 = __half22float2(*(half2*)&u.z);
        float2 f3 = __half22float2(*(half2*)&u.w);
        a0 += f0.x; a1 += f0.y; a2 += f1.x; a3 += f1.y;
        a4 += f2.x; a5 += f2.y; a6 += f3.x; a7 += f3.y;
    }
    float inv = 1.f / fmaxf((float)(r1 - r0), 1.f);
    half2 p0 = __floats2half2_rn(a0 * inv, a1 * inv);
    half2 p1 = __floats2half2_rn(a2 * inv, a3 * inv);
    half2 p2 = __floats2half2_rn(a4 * inv, a5 * inv);
    half2 p3 = __floats2half2_rn(a6 * inv, a7 * inv);
    uint4 pk = make_uint4(*(uint32_t*)&p0, *(uint32_t*)&p1,
                          *(uint32_t*)&p2, *(uint32_t*)&p3);
    ((uint4*)g_aggh)[(size_t)node * 16 + l16] = pk;
}

// ---------------------------------------------------------------------------
// 7. Layer 1 output GEMM + relu, fp16 mma.m16n8k16 (R12-proven version).
// ---------------------------------------------------------------------------
#define KB 32
#define ASTR 40
__global__ __launch_bounds__(256) void out_kernel(
    const float* __restrict__ bias, float* __restrict__ out, int n) {
    __shared__ __align__(16) __half sA[128][ASTR];
    __shared__ __align__(16) __half sB[128][ASTR];

    int tid = threadIdx.x;
    int wid = tid >> 5;
    int lane = tid & 31;
    int wm = wid >> 1;
    int wn = wid & 1;
    int gid = lane >> 2;
    int tg = lane & 3;
    int n0 = blockIdx.x * 128;

    float acc[2][8][4];
#pragma unroll
    for (int mt = 0; mt < 2; mt++)
#pragma unroll
        for (int nt = 0; nt < 8; nt++)
#pragma unroll
            for (int i = 0; i < 4; i++) acc[mt][nt][i] = 0.f;

    for (int kc = 0; kc < 2 * DG; kc += KB) {
        __syncthreads();
        {
            const __half* src = (kc < DG) ? g_aggh : g_hh;
            int ka = kc & (DG - 1);
#pragma unroll
            for (int q = 0; q < 2; q++) {
                int idx = tid + q * 256;
                int r = idx >> 2;
                int part = idx & 3;
                uint4 v = make_uint4(0, 0, 0, 0);
                if (n0 + r < n)
                    v = *(const uint4*)(src + (size_t)(n0 + r) * DG + ka + part * 8);
                *(uint4*)&sA[r][part * 8] = v;
            }
        }
        {
#pragma unroll
            for (int q = 0; q < 2; q++) {
                int idx = tid + q * 256;
                int r = idx >> 2;
                int part = idx & 3;
                uint4 v = *(const uint4*)(g_wh + (size_t)r * 2 * DG + kc + part * 8);
                *(uint4*)&sB[r][part * 8] = v;
            }
        }
        __syncthreads();

#pragma unroll
        for (int ks = 0; ks < 2; ks++) {
            int ko = ks * 16;
            uint32_t bf[8][2];
#pragma unroll
            for (int nt = 0; nt < 8; nt++) {
                int ncol = wn * 64 + nt * 8 + gid;
                bf[nt][0] = *(uint32_t*)&sB[ncol][ko + 2 * tg];
                bf[nt][1] = *(uint32_t*)&sB[ncol][ko + 2 * tg + 8];
            }
#pragma unroll
            for (int mt = 0; mt < 2; mt++) {
                int r = wm * 32 + mt * 16 + gid;
                uint32_t a0 = *(uint32_t*)&sA[r][ko + 2 * tg];
                uint32_t a1 = *(uint32_t*)&sA[r + 8][ko + 2 * tg];
                uint32_t a2 = *(uint32_t*)&sA[r][ko + 2 * tg + 8];
                uint32_t a3 = *(uint32_t*)&sA[r + 8][ko + 2 * tg + 8];
#pragma unroll
                for (int nt = 0; nt < 8; nt++) {
                    asm volatile(
                        "mma.sync.aligned.m16n8k16.row.col.f32.f16.f16.f32 "
                        "{%0,%1,%2,%3}, {%4,%5,%6,%7}, {%8,%9}, {%0,%1,%2,%3};"
                        : "+f"(acc[mt][nt][0]), "+f"(acc[mt][nt][1]),
                          "+f"(acc[mt][nt][2]), "+f"(acc[mt][nt][3])
                        : "r"(a0), "r"(a1), "r"(a2), "r"(a3),
                          "r"(bf[nt][0]), "r"(bf[nt][1]));
                }
            }
        }
    }

#pragma unroll
    for (int nt = 0; nt < 8; nt++) {
        int col = wn * 64 + nt * 8 + 2 * tg;
        float2 bv = *(const float2*)&bias[col];
#pragma unroll
        for (int mt = 0; mt < 2; mt++) {
            int row = n0 + wm * 32 + mt * 16 + gid;
            if (row < n) {
                float2 o;
                o.x = fmaxf(acc[mt][nt][0] + bv.x, 0.f);
                o.y = fmaxf(acc[mt][nt][1] + bv.y, 0.f);
                *(float2*)&out[(size_t)row * DG + col] = o;
            }
            if (row + 8 < n) {
                float2 o;
                o.x = fmaxf(acc[mt][nt][2] + bv.x, 0.f);
                o.y = fmaxf(acc[mt][nt][3] + bv.y, 0.f);
                *(float2*)&out[(size_t)(row + 8) * DG + col] = o;
            }
        }
    }
}

// ---------------------------------------------------------------------------
extern "C" void kernel_launch(void* const* d_in, const int* in_sizes, int n_in,
                              void* d_out, int out_size) {
    const float* x   = (const float*)d_in[0];
    const int*   ei  = (const int*)d_in[1];
    const float* Wl0 = (const float*)d_in[2];
    const float* Wr0 = (const float*)d_in[3];
    const float* b0  = (const float*)d_in[4];
    const float* Wl1 = (const float*)d_in[5];
    const float* Wr1 = (const float*)d_in[6];
    const float* b1  = (const float*)d_in[7];
    const float* g   = (const float*)d_in[8];
    const float* be  = (const float*)d_in[9];
    float* out = (float*)d_out;

    int n  = in_sizes[0] / 3;
    int nE = in_sizes[1] / 2;
    int nb = (n + SCB - 1) / SCB;
    int prepN = (n > 2 * DG * DG) ? n : 2 * DG * DG;
    int e4threads = (nE + 3) / 4;
    int nbFill = (e4threads + 255) / 256;
    int nbL0 = (n + 8 * NPW - 1) / (8 * NPW);   // 8 warps/block, NPW nodes/warp

    prep_kernel<<<(prepN + 255) / 256, 256>>>(Wl1, Wr1, n);
    edge0_kernel<<<(e4threads + 255) / 256, 256>>>(x, ei, nE);
    bsum_kernel<<<nb, 256>>>(n);
    scan_chunk_kernel<<<nb, 256>>>(nb, n);
    fill_layer0_kernel<<<nbFill + nbL0, 256>>>(ei, nE, nbFill,
                                               x, Wl0, Wr0, b0, g, be, n);
    int aggWarps = (n + 1) / 2;
    agg_kernel<<<(aggWarps * 32 + 255) / 256, 256>>>(n);
    out_kernel<<<(n + 127) / 128, 256>>>(b1, out, n);
}

// round 15
// speedup vs baseline: 1.0935x; 1.0194x over previous
#include <cuda_runtime.h>
#include <cuda_fp16.h>
#include <cstdint>

#define DG 128
#define MAXN 100000
#define MAXE 1600000
#define SCB 1024
#define MAXB ((MAXN + SCB - 1) / SCB)

// Scratch (device globals — no allocation allowed).
__device__ __align__(16) float g_agg0[MAXN * 4];   // x,y,z = sum x[src]; w = deg
__device__ int g_cursor[MAXN];
__device__ int g_rowptr[MAXN + 1];
__device__ int g_csrc[MAXE];
__device__ int g_bsum[MAXB];
__device__ __align__(16) __half g_hh[MAXN * DG];    // h after layer0+LN (fp16)
__device__ __align__(16) __half g_aggh[MAXN * DG];  // layer1 mean-agg (fp16)
__device__ __align__(16) __half g_wh[2 * DG * DG];  // [n][k] fp16 fused weights

// ---------------------------------------------------------------------------
// 1a. Prep: zero g_agg0 (critical path — needed by edge0).
// ---------------------------------------------------------------------------
__global__ void prep_kernel(int n) {
    int t = blockIdx.x * blockDim.x + threadIdx.x;
    if (t < n) ((float4*)g_agg0)[t] = make_float4(0.f, 0.f, 0.f, 0.f);
}

// 1b. Weight fuse/convert (side stream — only needed by out_kernel).
__global__ void convw_kernel(const float* __restrict__ Wl,
                             const float* __restrict__ Wr) {
    int t = blockIdx.x * blockDim.x + threadIdx.x;
    int k = t >> 7, nn = t & 127;
    float v = (k < DG) ? Wl[k * DG + nn] : Wr[(k - DG) * DG + nn];
    g_wh[nn * 2 * DG + k] = __float2half_rn(v);
}

// ---------------------------------------------------------------------------
// 2. Edge pass 0: scatter x[src] (3 dims) + degree, one float4 RED per edge.
// ---------------------------------------------------------------------------
__global__ void edge0_kernel(const float* __restrict__ x,
                             const int* __restrict__ ei, int nE) {
    int t = blockIdx.x * blockDim.x + threadIdx.x;
    int e4 = t * 4;
    if (e4 + 4 <= nE) {
        int4 ss = *(const int4*)(ei + e4);
        int4 dd = *(const int4*)(ei + nE + e4);
        float4 v0 = make_float4(x[3 * ss.x], x[3 * ss.x + 1], x[3 * ss.x + 2], 1.f);
        float4 v1 = make_float4(x[3 * ss.y], x[3 * ss.y + 1], x[3 * ss.y + 2], 1.f);
        float4 v2 = make_float4(x[3 * ss.z], x[3 * ss.z + 1], x[3 * ss.z + 2], 1.f);
        float4 v3 = make_float4(x[3 * ss.w], x[3 * ss.w + 1], x[3 * ss.w + 2], 1.f);
        atomicAdd((float4*)(g_agg0 + 4 * (size_t)dd.x), v0);
        atomicAdd((float4*)(g_agg0 + 4 * (size_t)dd.y), v1);
        atomicAdd((float4*)(g_agg0 + 4 * (size_t)dd.z), v2);
        atomicAdd((float4*)(g_agg0 + 4 * (size_t)dd.w), v3);
    } else {
        for (int e = e4; e < nE; e++) {
            int s = ei[e], d = ei[nE + e];
            float4 v = make_float4(x[3 * s], x[3 * s + 1], x[3 * s + 2], 1.f);
            atomicAdd((float4*)(g_agg0 + 4 * (size_t)d), v);
        }
    }
}

// ---------------------------------------------------------------------------
// 3. Per-chunk degree sums (degree read from g_agg0.w).
// ---------------------------------------------------------------------------
__global__ __launch_bounds__(256) void bsum_kernel(int n) {
    int base = blockIdx.x * SCB;
    int t = threadIdx.x;
    int s = 0;
#pragma unroll
    for (int q = 0; q < 4; q++) {
        int i = base + t + q * 256;
        if (i < n) s += (int)g_agg0[4 * (size_t)i + 3];
    }
#pragma unroll
    for (int o = 16; o; o >>= 1) s += __shfl_xor_sync(0xffffffffu, s, o);
    __shared__ int wt[8];
    if ((t & 31) == 0) wt[t >> 5] = s;
    __syncthreads();
    if (t == 0) {
        int tot = 0;
#pragma unroll
        for (int i = 0; i < 8; i++) tot += wt[i];
        g_bsum[blockIdx.x] = tot;
    }
}

// ---------------------------------------------------------------------------
// 4. Scan: each block scans the <=128 block sums for its offset, then does
//    its in-chunk exclusive scan -> rowptr & cursor.
// ---------------------------------------------------------------------------
__global__ __launch_bounds__(256) void scan_chunk_kernel(int nb, int n) {
    __shared__ int sincl[128];
    int t = threadIdx.x;
    int lane = t & 31, wid = t >> 5;

    if (t < 128) {
        int v = (t < nb) ? g_bsum[t] : 0;
        int incl = v;
#pragma unroll
        for (int o = 1; o < 32; o <<= 1) {
            int u = __shfl_up_sync(0xffffffffu, incl, o);
            if (lane >= o) incl += u;
        }
        sincl[t] = incl;
    }
    __syncthreads();
    if (t == 0) {
        int o1 = sincl[31], o2 = sincl[63], o3 = sincl[95];
        for (int i = 32; i < 64; i++) sincl[i] += o1;
        o2 += o1;
        for (int i = 64; i < 96; i++) sincl[i] += o2;
        o3 += o2;
        for (int i = 96; i < 128; i++) sincl[i] += o3;
    }
    __syncthreads();
    int boff = (blockIdx.x == 0) ? 0 : sincl[blockIdx.x - 1];
    if (blockIdx.x == 0 && t == 0) g_rowptr[n] = sincl[nb - 1];

    int base = blockIdx.x * SCB;
    int i0 = base + t * 4;
    int d0 = (i0 + 0 < n) ? (int)g_agg0[4 * (size_t)(i0 + 0) + 3] : 0;
    int d1 = (i0 + 1 < n) ? (int)g_agg0[4 * (size_t)(i0 + 1) + 3] : 0;
    int d2 = (i0 + 2 < n) ? (int)g_agg0[4 * (size_t)(i0 + 2) + 3] : 0;
    int d3 = (i0 + 3 < n) ? (int)g_agg0[4 * (size_t)(i0 + 3) + 3] : 0;
    int s = d0 + d1 + d2 + d3;

    int incl = s;
#pragma unroll
    for (int o = 1; o < 32; o <<= 1) {
        int u = __shfl_up_sync(0xffffffffu, incl, o);
        if (lane >= o) incl += u;
    }
    __shared__ int wt[8];
    if (lane == 31) wt[wid] = incl;
    __syncthreads();
    if (t == 0) {
        int run = 0;
#pragma unroll
        for (int i = 0; i < 8; i++) { int u = wt[i]; wt[i] = run; run += u; }
    }
    __syncthreads();
    int run = incl - s + wt[wid] + boff;
    if (i0 + 0 < n) { g_rowptr[i0 + 0] = run; g_cursor[i0 + 0] = run; run += d0; }
    if (i0 + 1 < n) { g_rowptr[i0 + 1] = run; g_cursor[i0 + 1] = run; run += d1; }
    if (i0 + 2 < n) { g_rowptr[i0 + 2] = run; g_cursor[i0 + 2] = run; run += d2; }
    if (i0 + 3 < n) { g_rowptr[i0 + 3] = run; g_cursor[i0 + 3] = run; run += d3; }
}

// ---------------------------------------------------------------------------
// 5a. Fill: CSR fill via cursor atomics, 4 edges/thread.
// ---------------------------------------------------------------------------
__global__ void fill_kernel(const int* __restrict__ ei, int nE) {
    int t = blockIdx.x * blockDim.x + threadIdx.x;
    int e4 = t * 4;
    if (e4 + 4 <= nE) {
        int4 ss = *(const int4*)(ei + e4);
        int4 dd = *(const int4*)(ei + nE + e4);
        int p0 = atomicAdd(&g_cursor[dd.x], 1);
        int p1 = atomicAdd(&g_cursor[dd.y], 1);
        int p2 = atomicAdd(&g_cursor[dd.z], 1);
        int p3 = atomicAdd(&g_cursor[dd.w], 1);
        g_csrc[p0] = ss.x;
        g_csrc[p1] = ss.y;
        g_csrc[p2] = ss.z;
        g_csrc[p3] = ss.w;
    } else {
        for (int e = e4; e < nE; e++) {
            int s = ei[e], d = ei[nE + e];
            int pos = atomicAdd(&g_cursor[d], 1);
            g_csrc[pos] = s;
        }
    }
}

// ---------------------------------------------------------------------------
// 5b. Layer 0 (side stream): warp handles NPW nodes, register-resident
//     weights, agg read directly from g_agg0. Emits h in fp16.
// ---------------------------------------------------------------------------
__device__ __forceinline__ float warp_sum(float v) {
#pragma unroll
    for (int o = 16; o; o >>= 1) v += __shfl_xor_sync(0xffffffffu, v, o);
    return v;
}

#define NPW 8
__global__ __launch_bounds__(256) void layer0_kernel(
    const float* __restrict__ x, const float* __restrict__ Wl,
    const float* __restrict__ Wr, const float* __restrict__ b,
    const float* __restrict__ g, const float* __restrict__ be, int n) {
    int warpIdx = blockIdx.x * 8 + (threadIdx.x >> 5);
    int node0 = warpIdx * NPW;
    if (node0 >= n) return;
    int lane = threadIdx.x & 31;
    int col = lane * 4;

    float4 wl0 = *(const float4*)&Wl[0 * DG + col];
    float4 wl1 = *(const float4*)&Wl[1 * DG + col];
    float4 wl2 = *(const float4*)&Wl[2 * DG + col];
    float4 wr0 = *(const float4*)&Wr[0 * DG + col];
    float4 wr1 = *(const float4*)&Wr[1 * DG + col];
    float4 wr2 = *(const float4*)&Wr[2 * DG + col];
    float4 bv  = *(const float4*)&b[col];
    float4 gv  = *(const float4*)&g[col];
    float4 bev = *(const float4*)&be[col];

#pragma unroll
    for (int i = 0; i < NPW; i++) {
        int w = node0 + i;
        if (w >= n) break;
        float4 a = ((const float4*)g_agg0)[w];
        float inv = 1.f / fmaxf(a.w, 1.f);
        float a0 = a.x * inv, a1 = a.y * inv, a2 = a.z * inv;
        float x0 = x[3 * w], x1 = x[3 * w + 1], x2 = x[3 * w + 2];

        float v0 = bv.x + a0 * wl0.x + a1 * wl1.x + a2 * wl2.x + x0 * wr0.x + x1 * wr1.x + x2 * wr2.x;
        float v1 = bv.y + a0 * wl0.y + a1 * wl1.y + a2 * wl2.y + x0 * wr0.y + x1 * wr1.y + x2 * wr2.y;
        float v2 = bv.z + a0 * wl0.z + a1 * wl1.z + a2 * wl2.z + x0 * wr0.z + x1 * wr1.z + x2 * wr2.z;
        float v3 = bv.w + a0 * wl0.w + a1 * wl1.w + a2 * wl2.w + x0 * wr0.w + x1 * wr1.w + x2 * wr2.w;
        v0 = fmaxf(v0, 0.f); v1 = fmaxf(v1, 0.f); v2 = fmaxf(v2, 0.f); v3 = fmaxf(v3, 0.f);

        float mu = warp_sum(v0 + v1 + v2 + v3) * (1.f / DG);
        float d0 = v0 - mu, d1 = v1 - mu, d2 = v2 - mu, d3 = v3 - mu;
        float var = warp_sum(d0 * d0 + d1 * d1 + d2 * d2 + d3 * d3) * (1.f / DG);
        float rs = rsqrtf(var + 1e-5f);

        half2 p0 = __floats2half2_rn(d0 * rs * gv.x + bev.x, d1 * rs * gv.y + bev.y);
        half2 p1 = __floats2half2_rn(d2 * rs * gv.z + bev.z, d3 * rs * gv.w + bev.w);
        uint2 pk = make_uint2(*(uint32_t*)&p0, *(uint32_t*)&p1);
        *(uint2*)(g_hh + (size_t)w * DG + col) = pk;
    }
}

// ---------------------------------------------------------------------------
// 6. Layer 1 aggregation: 16 lanes per node (2 nodes/warp), uint4 loads.
// ---------------------------------------------------------------------------
__global__ __launch_bounds__(256) void agg_kernel(int n) {
    int gw = (blockIdx.x * blockDim.x + threadIdx.x) >> 5;
    int lane = threadIdx.x & 31;
    int node = gw * 2 + (lane >> 4);
    if (node >= n) return;
    int l16 = lane & 15;
    int r0 = g_rowptr[node], r1 = g_rowptr[node + 1];
    const uint4* hh = (const uint4*)g_hh;

    float a0 = 0.f, a1 = 0.f, a2 = 0.f, a3 = 0.f;
    float a4 = 0.f, a5 = 0.f, a6 = 0.f, a7 = 0.f;
    int j = r0;
    for (; j + 4 <= r1; j += 4) {
        uint4 u[4];
#pragma unroll
        for (int q = 0; q < 4; q++) {
            int s = g_csrc[j + q];
            u[q] = hh[(size_t)s * 16 + l16];
        }
#pragma unroll
        for (int q = 0; q < 4; q++) {
            float2 f0 = __half22float2(*(half2*)&u[q].x);
            float2 f1 = __half22float2(*(half2*)&u[q].y);
            float2 f2 = __half22float2(*(half2*)&u[q].z);
            float2 f3 = __half22float2(*(half2*)&u[q].w);
            a0 += f0.x; a1 += f0.y; a2 += f1.x; a3 += f1.y;
            a4 += f2.x; a5 += f2.y; a6 += f3.x; a7 += f3.y;
        }
    }
    for (; j < r1; j++) {
        int s = g_csrc[j];
        uint4 u = hh[(size_t)s * 16 + l16];
        float2 f0 = __half22float2(*(half2*)&u.x);
        float2 f1 = __half22float2(*(half2*)&u.y);
        float2 f2 = __half22float2(*(half2*)&u.z);
        float2 f3 = __half22float2(*(half2*)&u.w);
        a0 += f0.x; a1 += f0.y; a2 += f1.x; a3 += f1.y;
        a4 += f2.x; a5 += f2.y; a6 += f3.x; a7 += f3.y;
    }
    float inv = 1.f / fmaxf((float)(r1 - r0), 1.f);
    half2 p0 = __floats2half2_rn(a0 * inv, a1 * inv);
    half2 p1 = __floats2half2_rn(a2 * inv, a3 * inv);
    half2 p2 = __floats2half2_rn(a4 * inv, a5 * inv);
    half2 p3 = __floats2half2_rn(a6 * inv, a7 * inv);
    uint4 pk = make_uint4(*(uint32_t*)&p0, *(uint32_t*)&p1,
                          *(uint32_t*)&p2, *(uint32_t*)&p3);
    ((uint4*)g_aggh)[(size_t)node * 16 + l16] = pk;
}

// ---------------------------------------------------------------------------
// 7. Layer 1 output GEMM + relu, fp16 mma.m16n8k16 (R12-proven version).
// ---------------------------------------------------------------------------
#define KB 32
#define ASTR 40
__global__ __launch_bounds__(256) void out_kernel(
    const float* __restrict__ bias, float* __restrict__ out, int n) {
    __shared__ __align__(16) __half sA[128][ASTR];
    __shared__ __align__(16) __half sB[128][ASTR];

    int tid = threadIdx.x;
    int wid = tid >> 5;
    int lane = tid & 31;
    int wm = wid >> 1;
    int wn = wid & 1;
    int gid = lane >> 2;
    int tg = lane & 3;
    int n0 = blockIdx.x * 128;

    float acc[2][8][4];
#pragma unroll
    for (int mt = 0; mt < 2; mt++)
#pragma unroll
        for (int nt = 0; nt < 8; nt++)
#pragma unroll
            for (int i = 0; i < 4; i++) acc[mt][nt][i] = 0.f;

    for (int kc = 0; kc < 2 * DG; kc += KB) {
        __syncthreads();
        {
            const __half* src = (kc < DG) ? g_aggh : g_hh;
            int ka = kc & (DG - 1);
#pragma unroll
            for (int q = 0; q < 2; q++) {
                int idx = tid + q * 256;
                int r = idx >> 2;
                int part = idx & 3;
                uint4 v = make_uint4(0, 0, 0, 0);
                if (n0 + r < n)
                    v = *(const uint4*)(src + (size_t)(n0 + r) * DG + ka + part * 8);
                *(uint4*)&sA[r][part * 8] = v;
            }
        }
        {
#pragma unroll
            for (int q = 0; q < 2; q++) {
                int idx = tid + q * 256;
                int r = idx >> 2;
                int part = idx & 3;
                uint4 v = *(const uint4*)(g_wh + (size_t)r * 2 * DG + kc + part * 8);
                *(uint4*)&sB[r][part * 8] = v;
            }
        }
        __syncthreads();

#pragma unroll
        for (int ks = 0; ks < 2; ks++) {
            int ko = ks * 16;
            uint32_t bf[8][2];
#pragma unroll
            for (int nt = 0; nt < 8; nt++) {
                int ncol = wn * 64 + nt * 8 + gid;
                bf[nt][0] = *(uint32_t*)&sB[ncol][ko + 2 * tg];
                bf[nt][1] = *(uint32_t*)&sB[ncol][ko + 2 * tg + 8];
            }
#pragma unroll
            for (int mt = 0; mt < 2; mt++) {
                int r = wm * 32 + mt * 16 + gid;
                uint32_t a0 = *(uint32_t*)&sA[r][ko + 2 * tg];
                uint32_t a1 = *(uint32_t*)&sA[r + 8][ko + 2 * tg];
                uint32_t a2 = *(uint32_t*)&sA[r][ko + 2 * tg + 8];
                uint32_t a3 = *(uint32_t*)&sA[r + 8][ko + 2 * tg + 8];
#pragma unroll
                for (int nt = 0; nt < 8; nt++) {
                    asm volatile(
                        "mma.sync.aligned.m16n8k16.row.col.f32.f16.f16.f32 "
                        "{%0,%1,%2,%3}, {%4,%5,%6,%7}, {%8,%9}, {%0,%1,%2,%3};"
                        : "+f"(acc[mt][nt][0]), "+f"(acc[mt][nt][1]),
                          "+f"(acc[mt][nt][2]), "+f"(acc[mt][nt][3])
                        : "r"(a0), "r"(a1), "r"(a2), "r"(a3),
                          "r"(bf[nt][0]), "r"(bf[nt][1]));
                }
            }
        }
    }

#pragma unroll
    for (int nt = 0; nt < 8; nt++) {
        int col = wn * 64 + nt * 8 + 2 * tg;
        float2 bv = *(const float2*)&bias[col];
#pragma unroll
        for (int mt = 0; mt < 2; mt++) {
            int row = n0 + wm * 32 + mt * 16 + gid;
            if (row < n) {
                float2 o;
                o.x = fmaxf(acc[mt][nt][0] + bv.x, 0.f);
                o.y = fmaxf(acc[mt][nt][1] + bv.y, 0.f);
                *(float2*)&out[(size_t)row * DG + col] = o;
            }
            if (row + 8 < n) {
                float2 o;
                o.x = fmaxf(acc[mt][nt][2] + bv.x, 0.f);
                o.y = fmaxf(acc[mt][nt][3] + bv.y, 0.f);
                *(float2*)&out[(size_t)(row + 8) * DG + col] = o;
            }
        }
    }
}

// ---------------------------------------------------------------------------
// Launch: forked-stream captured graph.
//   main:  prep_zero -> edge0 -> bsum -> scan -> fill -> (join) agg -> out
//   side:  convw (from start) ; layer0 (after edge0)
// ---------------------------------------------------------------------------
extern "C" void kernel_launch(void* const* d_in, const int* in_sizes, int n_in,
                              void* d_out, int out_size) {
    const float* x   = (const float*)d_in[0];
    const int*   ei  = (const int*)d_in[1];
    const float* Wl0 = (const float*)d_in[2];
    const float* Wr0 = (const float*)d_in[3];
    const float* b0  = (const float*)d_in[4];
    const float* Wl1 = (const float*)d_in[5];
    const float* Wr1 = (const float*)d_in[6];
    const float* b1  = (const float*)d_in[7];
    const float* g   = (const float*)d_in[8];
    const float* be  = (const float*)d_in[9];
    float* out = (float*)d_out;

    int n  = in_sizes[0] / 3;
    int nE = in_sizes[1] / 2;
    int nb = (n + SCB - 1) / SCB;
    int e4threads = (nE + 3) / 4;
    int nbL0 = (n + 8 * NPW - 1) / (8 * NPW);

    cudaStream_t s2;
    cudaStreamCreateWithFlags(&s2, cudaStreamNonBlocking);
    cudaEvent_t e0, e1, e2;
    cudaEventCreateWithFlags(&e0, cudaEventDisableTiming);
    cudaEventCreateWithFlags(&e1, cudaEventDisableTiming);
    cudaEventCreateWithFlags(&e2, cudaEventDisableTiming);

    // fork side stream from the capture-origin (legacy default) stream
    cudaEventRecord(e0, 0);
    cudaStreamWaitEvent(s2, e0, 0);
    convw_kernel<<<(2 * DG * DG) / 256, 256, 0, s2>>>(Wl1, Wr1);

    // main: zero + edge scatter
    prep_kernel<<<(n + 255) / 256, 256>>>(n);
    edge0_kernel<<<(e4threads + 255) / 256, 256>>>(x, ei, nE);
    cudaEventRecord(e1, 0);

    // side: layer0 after edge0
    cudaStreamWaitEvent(s2, e1, 0);
    layer0_kernel<<<nbL0, 256, 0, s2>>>(x, Wl0, Wr0, b0, g, be, n);
    cudaEventRecord(e2, s2);

    // main: CSR build
    bsum_kernel<<<nb, 256>>>(n);
    scan_chunk_kernel<<<nb, 256>>>(nb, n);
    fill_kernel<<<(e4threads + 255) / 256, 256>>>(ei, nE);

    // join side stream, then dependent phases
    cudaStreamWaitEvent(0, e2, 0);
    int aggWarps = (n + 1) / 2;
    agg_kernel<<<(aggWarps * 32 + 255) / 256, 256>>>(n);
    out_kernel<<<(n + 127) / 128, 256>>>(b1, out, n);
    // streams/events intentionally not destroyed: kernel_launch is called a
    // handful of times (correctness + capture); replays execute the graph.
}